// round 4
// baseline (speedup 1.0000x reference)
#include <cuda_runtime.h>

// Problem constants
#define NPTS        8192
#define BROWS       4096
#define KTOT        (NPTS * 3)            // 24576 floats per row
#define K4          (KTOT / 4)            // 6144 float4 per row

// Main kernel config: 2 CTAs per SM for latency hiding.
#define GRID_MAIN    304                  // 2 persistent CTAs per SM
#define THREADS_MAIN 512
#define NWARPS       (THREADS_MAIN / 32)  // 16
#define NTILES       6
#define TILE_K4      (K4 / NTILES)        // 1024 float4 per tile
#define UNROLL       (TILE_K4 / THREADS_MAIN) // 2 float4 per thread per tile
#define MAX_LROWS    ((BROWS + GRID_MAIN - 1) / GRID_MAIN) // 14

// Precomputed flattened weights, SoA by output index j. 288 KB device scratch.
__device__ float g_wf[3][KTOT];

__device__ __forceinline__ float softplusf(float x) {
    return fmaxf(x, 0.0f) + log1pf(expf(-fabsf(x)));
}

// ---------------------------------------------------------------------------
// Kernel 1: build W = M^T M per integration point, expand to SoA flat layout.
// ---------------------------------------------------------------------------
__global__ void symm_prep_kernel(const float* __restrict__ weight) {
    int n = blockIdx.x * blockDim.x + threadIdx.x;
    if (n >= NPTS) return;

    const float* w = weight + n * 6;
    float a = softplusf(w[0]);
    float b = w[1];
    float c = w[2];
    float d = softplusf(w[3]);
    float e = w[4];
    float f = softplusf(w[5]);

    float m00 = a * a;
    float m01 = a * b;
    float m02 = a * c;
    float m11 = b * b + d * d;
    float m12 = b * c + d * e;
    float m22 = c * c + e * e + f * f;

    int k = 3 * n;
    g_wf[0][k + 0] = m00; g_wf[0][k + 1] = m01; g_wf[0][k + 2] = m02;
    g_wf[1][k + 0] = m01; g_wf[1][k + 1] = m11; g_wf[1][k + 2] = m12;
    g_wf[2][k + 0] = m02; g_wf[2][k + 1] = m12; g_wf[2][k + 2] = m22;
}

// ---------------------------------------------------------------------------
// Kernel 2: register-resident W per K-tile, R=2 row pairs, 2 CTAs/SM.
// Shuffle tree shortened to 3 steps (offsets 16/8/4): after the butterfly,
// lanes 0..3 hold disjoint 8-lane group sums -> 4 partials per warp to smem.
// ---------------------------------------------------------------------------
__global__ void __launch_bounds__(THREADS_MAIN, 2)
symm_main_kernel(const float* __restrict__ x,
                 const float* __restrict__ bias,
                 float* __restrict__ out) {
    __shared__ float part[MAX_LROWS][NWARPS * 4][3];

    const int tid  = threadIdx.x;
    const int wid  = tid >> 5;
    const int lane = tid & 31;
    const int bid  = blockIdx.x;

    const float4* __restrict__ x4  = reinterpret_cast<const float4*>(x);
    const float4* __restrict__ wf0 = reinterpret_cast<const float4*>(g_wf[0]);
    const float4* __restrict__ wf1 = reinterpret_cast<const float4*>(g_wf[1]);
    const float4* __restrict__ wf2 = reinterpret_cast<const float4*>(g_wf[2]);

    for (int tile = 0; tile < NTILES; ++tile) {
        const int base4 = tile * TILE_K4;

        // W slice for this tile, registers (24 floats).
        float4 w0r[UNROLL], w1r[UNROLL], w2r[UNROLL];
#pragma unroll
        for (int i = 0; i < UNROLL; ++i) {
            int idx = base4 + i * THREADS_MAIN + tid;
            w0r[i] = wf0[idx];
            w1r[i] = wf1[idx];
            w2r[i] = wf2[idx];
        }

        for (int p = 0; ; ++p) {
            const int r0 = bid + (2 * p) * GRID_MAIN;
            if (r0 >= BROWS) break;
            const int r1 = r0 + GRID_MAIN;
            const bool has_r1 = (r1 < BROWS);

            const float4* __restrict__ xr0 = x4 + (size_t)r0 * K4 + base4;
            const float4* __restrict__ xr1 = x4 + (size_t)(has_r1 ? r1 : r0) * K4 + base4;

            // 4 independent LDG.128 up front.
            float4 xv0[UNROLL], xv1[UNROLL];
#pragma unroll
            for (int i = 0; i < UNROLL; ++i) {
                xv0[i] = __ldcs(&xr0[i * THREADS_MAIN + tid]);
                xv1[i] = __ldcs(&xr1[i * THREADS_MAIN + tid]);
            }

            float a0 = 0.0f, a1 = 0.0f, a2 = 0.0f;
            float b0 = 0.0f, b1 = 0.0f, b2 = 0.0f;
#pragma unroll
            for (int i = 0; i < UNROLL; ++i) {
                a0 = fmaf(xv0[i].x, w0r[i].x, a0); a0 = fmaf(xv0[i].y, w0r[i].y, a0);
                a0 = fmaf(xv0[i].z, w0r[i].z, a0); a0 = fmaf(xv0[i].w, w0r[i].w, a0);
                a1 = fmaf(xv0[i].x, w1r[i].x, a1); a1 = fmaf(xv0[i].y, w1r[i].y, a1);
                a1 = fmaf(xv0[i].z, w1r[i].z, a1); a1 = fmaf(xv0[i].w, w1r[i].w, a1);
                a2 = fmaf(xv0[i].x, w2r[i].x, a2); a2 = fmaf(xv0[i].y, w2r[i].y, a2);
                a2 = fmaf(xv0[i].z, w2r[i].z, a2); a2 = fmaf(xv0[i].w, w2r[i].w, a2);

                b0 = fmaf(xv1[i].x, w0r[i].x, b0); b0 = fmaf(xv1[i].y, w0r[i].y, b0);
                b0 = fmaf(xv1[i].z, w0r[i].z, b0); b0 = fmaf(xv1[i].w, w0r[i].w, b0);
                b1 = fmaf(xv1[i].x, w1r[i].x, b1); b1 = fmaf(xv1[i].y, w1r[i].y, b1);
                b1 = fmaf(xv1[i].z, w1r[i].z, b1); b1 = fmaf(xv1[i].w, w1r[i].w, b1);
                b2 = fmaf(xv1[i].x, w2r[i].x, b2); b2 = fmaf(xv1[i].y, w2r[i].y, b2);
                b2 = fmaf(xv1[i].z, w2r[i].z, b2); b2 = fmaf(xv1[i].w, w2r[i].w, b2);
            }

            // 3-step butterfly (16/8/4): lanes 0..3 end with disjoint
            // 8-lane group sums covering all 32 lanes.
#pragma unroll
            for (int off = 16; off >= 4; off >>= 1) {
                a0 += __shfl_xor_sync(0xffffffffu, a0, off);
                b0 += __shfl_xor_sync(0xffffffffu, b0, off);
                a1 += __shfl_xor_sync(0xffffffffu, a1, off);
                b1 += __shfl_xor_sync(0xffffffffu, b1, off);
                a2 += __shfl_xor_sync(0xffffffffu, a2, off);
                b2 += __shfl_xor_sync(0xffffffffu, b2, off);
            }

            if (lane < 4) {
                const int lr0 = 2 * p;
                const int col = wid * 4 + lane;
                if (tile == 0) {
                    part[lr0][col][0] = a0;
                    part[lr0][col][1] = a1;
                    part[lr0][col][2] = a2;
                    if (has_r1) {
                        part[lr0 + 1][col][0] = b0;
                        part[lr0 + 1][col][1] = b1;
                        part[lr0 + 1][col][2] = b2;
                    }
                } else {
                    part[lr0][col][0] += a0;
                    part[lr0][col][1] += a1;
                    part[lr0][col][2] += a2;
                    if (has_r1) {
                        part[lr0 + 1][col][0] += b0;
                        part[lr0 + 1][col][1] += b1;
                        part[lr0 + 1][col][2] += b2;
                    }
                }
            }
        }
    }

    __syncthreads();

    // Final cross-warp reduction (64 partials per row) + bias.
    const int nrows = (BROWS - 1 - bid) / GRID_MAIN + 1;  // 13 or 14
    for (int o = tid; o < nrows * 3; o += THREADS_MAIN) {
        int lr = o / 3;
        int j  = o - lr * 3;
        float s = 0.0f;
#pragma unroll
        for (int w = 0; w < NWARPS * 4; ++w) s += part[lr][w][j];
        int row = bid + lr * GRID_MAIN;
        out[row * 3 + j] = s + (float)NPTS * __ldg(&bias[j]);
    }
}

// ---------------------------------------------------------------------------
extern "C" void kernel_launch(void* const* d_in, const int* in_sizes, int n_in,
                              void* d_out, int out_size) {
    const float* x      = (const float*)d_in[0];
    const float* weight = (const float*)d_in[1];
    const float* bias   = (const float*)d_in[2];
    float*       out    = (float*)d_out;
    (void)in_sizes; (void)n_in; (void)out_size;

    symm_prep_kernel<<<(NPTS + 255) / 256, 256>>>(weight);
    symm_main_kernel<<<GRID_MAIN, THREADS_MAIN>>>(x, bias, out);
}

// round 5
// speedup vs baseline: 1.0343x; 1.0343x over previous
#include <cuda_runtime.h>

// Problem constants
#define NPTS        8192
#define BROWS       4096
#define KTOT        (NPTS * 3)            // 24576 floats per row
#define K4          (KTOT / 4)            // 6144 float4 per row

// Main kernel config: single fused kernel, 1 CTA/SM.
#define GRID_MAIN    152
#define THREADS_MAIN 512
#define NWARPS       (THREADS_MAIN / 32)  // 16
#define NTILES       4
#define TILE_K4      (K4 / NTILES)        // 1536 float4 per tile
#define UNROLL       (TILE_K4 / THREADS_MAIN) // 3 float4 per thread per tile
#define MAX_LROWS    ((BROWS + GRID_MAIN - 1) / GRID_MAIN) // 27

__device__ __forceinline__ float softplus_fast(float x) {
    // softplus = max(x,0) + log(1 + exp(-|x|)); fast intrinsics (err ~1e-6 rel,
    // tolerance is 1e-3).
    float e = __expf(-fabsf(x));
    return fmaxf(x, 0.0f) + __logf(1.0f + e);
}

// Symmetric M^T M packed as 6 uniques.
struct Sym6 { float s00, s01, s02, s11, s12, s22; };

__device__ __forceinline__ Sym6 make_sym(const float* __restrict__ w) {
    float a = softplus_fast(w[0]);
    float b = w[1];
    float c = w[2];
    float d = softplus_fast(w[3]);
    float e = w[4];
    float f = softplus_fast(w[5]);
    Sym6 s;
    s.s00 = a * a;
    s.s01 = a * b;
    s.s02 = a * c;
    s.s11 = fmaf(b, b, d * d);
    s.s12 = fmaf(b, c, d * e);
    s.s22 = fmaf(c, c, fmaf(e, e, f * f));
    return s;
}

struct PairBuf {
    float4 v0[UNROLL];
    float4 v1[UNROLL];
};

__device__ __forceinline__ void load_pair(PairBuf& buf,
                                          const float4* __restrict__ x4,
                                          int r0, int r1, int base4, int tid) {
    const float4* __restrict__ xr0 = x4 + (size_t)r0 * K4 + base4;
    const float4* __restrict__ xr1 = x4 + (size_t)r1 * K4 + base4;
#pragma unroll
    for (int i = 0; i < UNROLL; ++i) {
        buf.v0[i] = __ldcs(&xr0[i * THREADS_MAIN + tid]);
        buf.v1[i] = __ldcs(&xr1[i * THREADS_MAIN + tid]);
    }
}

// ---------------------------------------------------------------------------
// Fused kernel: out[b,j] = sum_k x[b,k] * W[j][k] + NPTS*bias[j], with the
// flattened W computed per-thread in registers from `weight` at tile setup
// (no prep kernel, no scratch buffer, single launch).  x streamed once,
// perfectly coalesced LDG.128 + evict-first; R=2 row pairs, ping-pong
// prefetch; W setup overlapped under pair-0's in-flight loads.
// ---------------------------------------------------------------------------
__global__ void __launch_bounds__(THREADS_MAIN, 1)
symm_fused_kernel(const float* __restrict__ x,
                  const float* __restrict__ weight,
                  const float* __restrict__ bias,
                  float* __restrict__ out) {
    __shared__ float part[MAX_LROWS][NWARPS][3];

    const int tid  = threadIdx.x;
    const int wid  = tid >> 5;
    const int lane = tid & 31;
    const int bid  = blockIdx.x;

    const float4* __restrict__ x4 = reinterpret_cast<const float4*>(x);

    const int nrows  = (BROWS - 1 - bid) / GRID_MAIN + 1;   // 26 or 27
    const int npairs = (nrows + 1) / 2;

    for (int tile = 0; tile < NTILES; ++tile) {
        const int base4 = tile * TILE_K4;

        PairBuf A, B;

        // Issue pair 0's loads FIRST so W setup latency hides under them.
        {
            int r0 = bid;
            int r1 = (r0 + GRID_MAIN < BROWS) ? r0 + GRID_MAIN : r0;
            load_pair(A, x4, r0, r1, base4, tid);
        }

        // Build this thread's W slice in registers from `weight`.
        // float4 i covers k = 4*idx .. 4*idx+3, spanning points n0, n0+1
        // with phase phi = k0 % 3.
        float4 w0r[UNROLL], w1r[UNROLL], w2r[UNROLL];
#pragma unroll
        for (int i = 0; i < UNROLL; ++i) {
            const int idx = base4 + i * THREADS_MAIN + tid;
            const int k0  = 4 * idx;
            const int n0  = k0 / 3;
            const int phi = k0 - 3 * n0;

            Sym6 S0 = make_sym(weight + (size_t)n0 * 6);
            Sym6 S1 = make_sym(weight + (size_t)(n0 + 1) * 6);

            if (phi == 0) {
                // slots: (n0,0) (n0,1) (n0,2) (n1,0)
                w0r[i] = make_float4(S0.s00, S0.s01, S0.s02, S1.s00);
                w1r[i] = make_float4(S0.s01, S0.s11, S0.s12, S1.s01);
                w2r[i] = make_float4(S0.s02, S0.s12, S0.s22, S1.s02);
            } else if (phi == 1) {
                // slots: (n0,1) (n0,2) (n1,0) (n1,1)
                w0r[i] = make_float4(S0.s01, S0.s02, S1.s00, S1.s01);
                w1r[i] = make_float4(S0.s11, S0.s12, S1.s01, S1.s11);
                w2r[i] = make_float4(S0.s12, S0.s22, S1.s02, S1.s12);
            } else {
                // slots: (n0,2) (n1,0) (n1,1) (n1,2)
                w0r[i] = make_float4(S0.s02, S1.s00, S1.s01, S1.s02);
                w1r[i] = make_float4(S0.s12, S1.s01, S1.s11, S1.s12);
                w2r[i] = make_float4(S0.s22, S1.s02, S1.s12, S1.s22);
            }
        }

        auto process = [&](const PairBuf& buf, int p) {
            const int  r1     = bid + (2 * p + 1) * GRID_MAIN;
            const bool has_r1 = (r1 < BROWS);

            float a0 = 0.0f, a1 = 0.0f, a2 = 0.0f;
            float b0 = 0.0f, b1 = 0.0f, b2 = 0.0f;
#pragma unroll
            for (int i = 0; i < UNROLL; ++i) {
                a0 = fmaf(buf.v0[i].x, w0r[i].x, a0); a0 = fmaf(buf.v0[i].y, w0r[i].y, a0);
                a0 = fmaf(buf.v0[i].z, w0r[i].z, a0); a0 = fmaf(buf.v0[i].w, w0r[i].w, a0);
                a1 = fmaf(buf.v0[i].x, w1r[i].x, a1); a1 = fmaf(buf.v0[i].y, w1r[i].y, a1);
                a1 = fmaf(buf.v0[i].z, w1r[i].z, a1); a1 = fmaf(buf.v0[i].w, w1r[i].w, a1);
                a2 = fmaf(buf.v0[i].x, w2r[i].x, a2); a2 = fmaf(buf.v0[i].y, w2r[i].y, a2);
                a2 = fmaf(buf.v0[i].z, w2r[i].z, a2); a2 = fmaf(buf.v0[i].w, w2r[i].w, a2);

                b0 = fmaf(buf.v1[i].x, w0r[i].x, b0); b0 = fmaf(buf.v1[i].y, w0r[i].y, b0);
                b0 = fmaf(buf.v1[i].z, w0r[i].z, b0); b0 = fmaf(buf.v1[i].w, w0r[i].w, b0);
                b1 = fmaf(buf.v1[i].x, w1r[i].x, b1); b1 = fmaf(buf.v1[i].y, w1r[i].y, b1);
                b1 = fmaf(buf.v1[i].z, w1r[i].z, b1); b1 = fmaf(buf.v1[i].w, w1r[i].w, b1);
                b2 = fmaf(buf.v1[i].x, w2r[i].x, b2); b2 = fmaf(buf.v1[i].y, w2r[i].y, b2);
                b2 = fmaf(buf.v1[i].z, w2r[i].z, b2); b2 = fmaf(buf.v1[i].w, w2r[i].w, b2);
            }

#pragma unroll
            for (int off = 16; off > 0; off >>= 1) {
                a0 += __shfl_xor_sync(0xffffffffu, a0, off);
                b0 += __shfl_xor_sync(0xffffffffu, b0, off);
                a1 += __shfl_xor_sync(0xffffffffu, a1, off);
                b1 += __shfl_xor_sync(0xffffffffu, b1, off);
                a2 += __shfl_xor_sync(0xffffffffu, a2, off);
                b2 += __shfl_xor_sync(0xffffffffu, b2, off);
            }

            if (lane == 0) {
                const int lr0 = 2 * p;
                if (tile == 0) {
                    part[lr0][wid][0] = a0;
                    part[lr0][wid][1] = a1;
                    part[lr0][wid][2] = a2;
                    if (has_r1) {
                        part[lr0 + 1][wid][0] = b0;
                        part[lr0 + 1][wid][1] = b1;
                        part[lr0 + 1][wid][2] = b2;
                    }
                } else {
                    part[lr0][wid][0] += a0;
                    part[lr0][wid][1] += a1;
                    part[lr0][wid][2] += a2;
                    if (has_r1) {
                        part[lr0 + 1][wid][0] += b0;
                        part[lr0 + 1][wid][1] += b1;
                        part[lr0 + 1][wid][2] += b2;
                    }
                }
            }
        };

        auto prefetch = [&](PairBuf& buf, int p) {
            int r0 = bid + (2 * p) * GRID_MAIN;
            int r1 = r0 + GRID_MAIN;
            if (r1 >= BROWS) r1 = r0;
            load_pair(buf, x4, r0, r1, base4, tid);
        };

        for (int p = 0; p < npairs; p += 2) {
            if (p + 1 < npairs) prefetch(B, p + 1);
            process(A, p);
            if (p + 1 < npairs) {
                if (p + 2 < npairs) prefetch(A, p + 2);
                process(B, p + 1);
            }
        }
    }

    __syncthreads();

    // Final cross-warp reduction + bias.
    for (int o = tid; o < nrows * 3; o += THREADS_MAIN) {
        int lr = o / 3;
        int j  = o - lr * 3;
        float s = 0.0f;
#pragma unroll
        for (int w = 0; w < NWARPS; ++w) s += part[lr][w][j];
        int row = bid + lr * GRID_MAIN;
        out[row * 3 + j] = s + (float)NPTS * __ldg(&bias[j]);
    }
}

// ---------------------------------------------------------------------------
extern "C" void kernel_launch(void* const* d_in, const int* in_sizes, int n_in,
                              void* d_out, int out_size) {
    const float* x      = (const float*)d_in[0];
    const float* weight = (const float*)d_in[1];
    const float* bias   = (const float*)d_in[2];
    float*       out    = (float*)d_out;
    (void)in_sizes; (void)n_in; (void)out_size;

    symm_fused_kernel<<<GRID_MAIN, THREADS_MAIN>>>(x, weight, bias, out);
}